// round 5
// baseline (speedup 1.0000x reference)
#include <cuda_runtime.h>
#include <cuda_bf16.h>
#include <math.h>

// ============================================================================
// DecoderAttention: embed -> causal self-attn -> cross-attn -> vocab proj
// B=4, S=512, ENC=1024, H=1024, VOCAB=32000
// Round 0: fp32 SIMT baseline. All GEMMs share one 128x128x16 tile kernel
// (8x8 register tile per thread, 256 threads). Attention = batched NT GEMM
// (scores) + row softmax + batched NN GEMM (P@V).
// ============================================================================

#define HID 1024
#define SQ 512
#define SE 1024
#define NB 4
#define VOCAB_N 32000

// ---------------- scratch (static device arrays; no runtime allocs) --------
__device__ float g_x[NB * SQ * HID];   // embeddings / cross-attn out
__device__ float g_q[NB * SQ * HID];   // Q (self then cross)
__device__ float g_k[NB * SE * HID];   // K (self uses first half)
__device__ float g_v[NB * SE * HID];   // V
__device__ float g_s[NB * SQ * SE];    // scores / probs
__device__ float g_a[NB * SQ * HID];   // self-attn out

// ---------------- embedding -------------------------------------------------
__global__ void embed_kernel(const int* __restrict__ tok,
                             const float* __restrict__ tok_emb,
                             const float* __restrict__ pos_emb,
                             float* __restrict__ x) {
    int bs = blockIdx.x;              // 0..B*S-1
    int s = bs & (SQ - 1);
    int t = tok[bs];
    const float4* te = (const float4*)(tok_emb + (size_t)t * HID);
    const float4* pe = (const float4*)(pos_emb + (size_t)s * HID);
    float4* xo = (float4*)(x + (size_t)bs * HID);
    for (int i = threadIdx.x; i < HID / 4; i += blockDim.x) {
        float4 a = te[i], b = pe[i];
        xo[i] = make_float4(a.x + b.x, a.y + b.y, a.z + b.z, a.w + b.w);
    }
}

// ---------------- GEMM NN: C[M,N] = A[M,K] @ B[K,N] (+bias) ----------------
#define BM 128
#define BN 128
#define BKT 16
#define TM 8
#define TN 8

__global__ __launch_bounds__(256)
void gemm_nn(const float* __restrict__ A, const float* __restrict__ B,
             const float* __restrict__ bias, float* __restrict__ C,
             int M, int N, int K,
             size_t sA, size_t sB, size_t sC) {
    A += (size_t)blockIdx.z * sA;
    B += (size_t)blockIdx.z * sB;
    C += (size_t)blockIdx.z * sC;

    __shared__ __align__(16) float As[BKT][BM];
    __shared__ __align__(16) float Bs[BKT][BN];

    int tid = threadIdx.x;
    int row0 = blockIdx.y * BM;
    int col0 = blockIdx.x * BN;
    int tx = tid & 15;
    int ty = tid >> 4;

    float acc[TM][TN] = {};

    for (int k0 = 0; k0 < K; k0 += BKT) {
        // A tile: 128x16 floats = 512 float4, 2 per thread; store transposed
        #pragma unroll
        for (int l = 0; l < 2; l++) {
            int fid = tid + l * 256;
            int m = fid >> 2;
            int k4 = fid & 3;
            float4 v = *(const float4*)(A + (size_t)(row0 + m) * K + k0 + k4 * 4);
            As[k4 * 4 + 0][m] = v.x;
            As[k4 * 4 + 1][m] = v.y;
            As[k4 * 4 + 2][m] = v.z;
            As[k4 * 4 + 3][m] = v.w;
        }
        // B tile: 16x128 floats = 512 float4, 2 per thread; direct
        #pragma unroll
        for (int l = 0; l < 2; l++) {
            int fid = tid + l * 256;
            int k = fid >> 5;
            int n4 = fid & 31;
            float4 v = *(const float4*)(B + (size_t)(k0 + k) * N + col0 + n4 * 4);
            ((float4*)&Bs[k][0])[n4] = v;
        }
        __syncthreads();
        #pragma unroll
        for (int kk = 0; kk < BKT; kk++) {
            float a[TM], b[TN];
            #pragma unroll
            for (int i = 0; i < TM; i++) a[i] = As[kk][ty * TM + i];
            #pragma unroll
            for (int j = 0; j < TN; j++) b[j] = Bs[kk][tx * TN + j];
            #pragma unroll
            for (int i = 0; i < TM; i++)
                #pragma unroll
                for (int j = 0; j < TN; j++)
                    acc[i][j] += a[i] * b[j];
        }
        __syncthreads();
    }

    #pragma unroll
    for (int i = 0; i < TM; i++) {
        int r = row0 + ty * TM + i;
        #pragma unroll
        for (int j = 0; j < TN; j += 4) {
            int c = col0 + tx * TN + j;
            float4 v = make_float4(acc[i][j], acc[i][j + 1], acc[i][j + 2], acc[i][j + 3]);
            if (bias) {
                v.x += bias[c]; v.y += bias[c + 1];
                v.z += bias[c + 2]; v.w += bias[c + 3];
            }
            *(float4*)(C + (size_t)r * N + c) = v;
        }
    }
}

// ---------------- GEMM NT: C[M,N] = A[M,K] @ B[N,K]^T (scores) -------------
__global__ __launch_bounds__(256)
void gemm_nt(const float* __restrict__ A, const float* __restrict__ B,
             float* __restrict__ C,
             int M, int N, int K,
             size_t sA, size_t sB, size_t sC) {
    A += (size_t)blockIdx.z * sA;
    B += (size_t)blockIdx.z * sB;
    C += (size_t)blockIdx.z * sC;

    __shared__ __align__(16) float As[BKT][BM];
    __shared__ __align__(16) float Bs[BKT][BN];

    int tid = threadIdx.x;
    int row0 = blockIdx.y * BM;
    int col0 = blockIdx.x * BN;
    int tx = tid & 15;
    int ty = tid >> 4;

    float acc[TM][TN] = {};

    for (int k0 = 0; k0 < K; k0 += BKT) {
        #pragma unroll
        for (int l = 0; l < 2; l++) {
            int fid = tid + l * 256;
            int m = fid >> 2;
            int k4 = fid & 3;
            float4 v = *(const float4*)(A + (size_t)(row0 + m) * K + k0 + k4 * 4);
            As[k4 * 4 + 0][m] = v.x;
            As[k4 * 4 + 1][m] = v.y;
            As[k4 * 4 + 2][m] = v.z;
            As[k4 * 4 + 3][m] = v.w;
        }
        // B is [N,K] row-major; load along K (contiguous), store transposed
        #pragma unroll
        for (int l = 0; l < 2; l++) {
            int fid = tid + l * 256;
            int n = fid >> 2;
            int k4 = fid & 3;
            float4 v = *(const float4*)(B + (size_t)(col0 + n) * K + k0 + k4 * 4);
            Bs[k4 * 4 + 0][n] = v.x;
            Bs[k4 * 4 + 1][n] = v.y;
            Bs[k4 * 4 + 2][n] = v.z;
            Bs[k4 * 4 + 3][n] = v.w;
        }
        __syncthreads();
        #pragma unroll
        for (int kk = 0; kk < BKT; kk++) {
            float a[TM], b[TN];
            #pragma unroll
            for (int i = 0; i < TM; i++) a[i] = As[kk][ty * TM + i];
            #pragma unroll
            for (int j = 0; j < TN; j++) b[j] = Bs[kk][tx * TN + j];
            #pragma unroll
            for (int i = 0; i < TM; i++)
                #pragma unroll
                for (int j = 0; j < TN; j++)
                    acc[i][j] += a[i] * b[j];
        }
        __syncthreads();
    }

    #pragma unroll
    for (int i = 0; i < TM; i++) {
        int r = row0 + ty * TM + i;
        #pragma unroll
        for (int j = 0; j < TN; j += 4) {
            int c = col0 + tx * TN + j;
            float4 v = make_float4(acc[i][j], acc[i][j + 1], acc[i][j + 2], acc[i][j + 3]);
            *(float4*)(C + (size_t)r * N + c) = v;
        }
    }
}

// ---------------- row softmax (scale 1/32, optional causal) -----------------
__device__ __forceinline__ float warpMaxf(float v) {
    #pragma unroll
    for (int o = 16; o > 0; o >>= 1) v = fmaxf(v, __shfl_xor_sync(0xffffffffu, v, o));
    return v;
}
__device__ __forceinline__ float warpSumf(float v) {
    #pragma unroll
    for (int o = 16; o > 0; o >>= 1) v += __shfl_xor_sync(0xffffffffu, v, o);
    return v;
}

__global__ void softmax_kernel(float* __restrict__ S, int L, int causal) {
    int row = blockIdx.x;
    int q = row & (SQ - 1);
    float* s = S + (size_t)row * L;
    int valid = causal ? (q + 1) : L;

    __shared__ float shm[8];
    __shared__ float shs[8];
    __shared__ float bmax, bsum;
    int lane = threadIdx.x & 31;
    int wid = threadIdx.x >> 5;

    float m = -INFINITY;
    for (int k = threadIdx.x; k < valid; k += 256) m = fmaxf(m, s[k]);
    m = warpMaxf(m);
    if (lane == 0) shm[wid] = m;
    __syncthreads();
    if (wid == 0) {
        float x = (lane < 8) ? shm[lane] : -INFINITY;
        x = warpMaxf(x);
        if (lane == 0) bmax = x;
    }
    __syncthreads();
    m = bmax;

    float sum = 0.f;
    for (int k = threadIdx.x; k < valid; k += 256) {
        float e = expf((s[k] - m) * 0.03125f);  // scale = 1/sqrt(1024)
        s[k] = e;
        sum += e;
    }
    sum = warpSumf(sum);
    if (lane == 0) shs[wid] = sum;
    __syncthreads();
    if (wid == 0) {
        float x = (lane < 8) ? shs[lane] : 0.f;
        x = warpSumf(x);
        if (lane == 0) bsum = x;
    }
    __syncthreads();
    float inv = 1.f / bsum;

    for (int k = threadIdx.x; k < L; k += 256)
        s[k] = (k < valid) ? s[k] * inv : 0.f;
}

// ---------------- launch ----------------------------------------------------
extern "C" void kernel_launch(void* const* d_in, const int* in_sizes, int n_in,
                              void* d_out, int out_size) {
    const float* enc   = (const float*)d_in[0];
    const int*   tok   = (const int*)d_in[1];
    const float* temb  = (const float*)d_in[2];
    const float* pemb  = (const float*)d_in[3];
    const float* Wq_s  = (const float*)d_in[4];
    const float* bq_s  = (const float*)d_in[5];
    const float* Wk_s  = (const float*)d_in[6];
    const float* bk_s  = (const float*)d_in[7];
    const float* Wv_s  = (const float*)d_in[8];
    const float* bv_s  = (const float*)d_in[9];
    const float* Wq_c  = (const float*)d_in[10];
    const float* bq_c  = (const float*)d_in[11];
    const float* Wk_c  = (const float*)d_in[12];
    const float* bk_c  = (const float*)d_in[13];
    const float* Wv_c  = (const float*)d_in[14];
    const float* bv_c  = (const float*)d_in[15];
    const float* Wout  = (const float*)d_in[16];
    const float* bout  = (const float*)d_in[17];
    float* out = (float*)d_out;

    float *x, *q, *k, *v, *s, *a;
    cudaGetSymbolAddress((void**)&x, g_x);
    cudaGetSymbolAddress((void**)&q, g_q);
    cudaGetSymbolAddress((void**)&k, g_k);
    cudaGetSymbolAddress((void**)&v, g_v);
    cudaGetSymbolAddress((void**)&s, g_s);
    cudaGetSymbolAddress((void**)&a, g_a);

    const int MQ = NB * SQ;   // 2048
    const int ME = NB * SE;   // 4096

    // 1. embeddings
    embed_kernel<<<MQ, 256>>>(tok, temb, pemb, x);

    // 2. self-attn projections
    gemm_nn<<<dim3(HID / BN, MQ / BM, 1), 256>>>(x, Wq_s, bq_s, q, MQ, HID, HID, 0, 0, 0);
    gemm_nn<<<dim3(HID / BN, MQ / BM, 1), 256>>>(x, Wk_s, bk_s, k, MQ, HID, HID, 0, 0, 0);
    gemm_nn<<<dim3(HID / BN, MQ / BM, 1), 256>>>(x, Wv_s, bv_s, v, MQ, HID, HID, 0, 0, 0);

    // 3. self-attn: scores (batched NT), causal softmax, P@V (batched NN)
    gemm_nt<<<dim3(SQ / BN, SQ / BM, NB), 256>>>(q, k, s, SQ, SQ, HID,
                                                 (size_t)SQ * HID, (size_t)SQ * HID, (size_t)SQ * SQ);
    softmax_kernel<<<MQ, 256>>>(s, SQ, 1);
    gemm_nn<<<dim3(HID / BN, SQ / BM, NB), 256>>>(s, v, nullptr, a, SQ, HID, SQ,
                                                  (size_t)SQ * SQ, (size_t)SQ * HID, (size_t)SQ * HID);

    // 4. cross-attn projections (K/V over encoder outputs)
    gemm_nn<<<dim3(HID / BN, MQ / BM, 1), 256>>>(a, Wq_c, bq_c, q, MQ, HID, HID, 0, 0, 0);
    gemm_nn<<<dim3(HID / BN, ME / BM, 1), 256>>>(enc, Wk_c, bk_c, k, ME, HID, HID, 0, 0, 0);
    gemm_nn<<<dim3(HID / BN, ME / BM, 1), 256>>>(enc, Wv_c, bv_c, v, ME, HID, HID, 0, 0, 0);

    // 5. cross-attn: scores, softmax, P@V -> reuse g_x
    gemm_nt<<<dim3(SE / BN, SQ / BM, NB), 256>>>(q, k, s, SQ, SE, HID,
                                                 (size_t)SQ * HID, (size_t)SE * HID, (size_t)SQ * SE);
    softmax_kernel<<<MQ, 256>>>(s, SE, 0);
    gemm_nn<<<dim3(HID / BN, SQ / BM, NB), 256>>>(s, v, nullptr, x, SQ, HID, SE,
                                                  (size_t)SQ * SE, (size_t)SE * HID, (size_t)SQ * HID);

    // 6. vocab projection (dominant GEMM: 2048 x 32000 x 1024)
    gemm_nn<<<dim3(VOCAB_N / BN, MQ / BM, 1), 256>>>(x, Wout, bout, out,
                                                     MQ, VOCAB_N, HID, 0, 0, 0);
}